// round 2
// baseline (speedup 1.0000x reference)
#include <cuda_runtime.h>

#define B_ 32
#define C_ 64
#define H_ 128
#define W_ 128
#define HW_ (H_*W_)
#define NTOT_ (B_*C_*HW_)

// Scratch for q,k,v projections (134 MB each) — static device arrays per harness rules.
__device__ float g_q[NTOT_];
__device__ float g_k[NTOT_];
__device__ float g_v[NTOT_];

typedef unsigned long long u64;

__device__ __forceinline__ u64 pack2(float lo, float hi) {
    u64 r;
    asm("mov.b64 %0, {%1, %2};" : "=l"(r) : "f"(lo), "f"(hi));
    return r;
}
__device__ __forceinline__ float2 unpack2(u64 v) {
    float2 f;
    asm("mov.b64 {%0, %1}, %2;" : "=f"(f.x), "=f"(f.y) : "l"(v));
    return f;
}
// Packed fp32 FMA: d = a*b + d elementwise on {lo,hi}. sm_100+ only.
__device__ __forceinline__ void ffma2(u64& d, u64 a, u64 b) {
    asm("fma.rn.f32x2 %0, %1, %2, %3;" : "=l"(d) : "l"(a), "l"(b), "l"(d));
}

// ---------------------------------------------------------------------------
// Kernel 1: q/k/v = W @ x + b  (per-pixel 64x64 channel mix)
// Grid (HW/512, B), 256 threads. Xs tile [64][512] + replicated-W pairs in smem.
// Thread = (warp og -> 8 output channels) x (lane -> 8 pixel pairs = 16 px).
// ---------------------------------------------------------------------------
#define PROJ_SMEM (C_*512*4 + C_*C_*8)

__global__ __launch_bounds__(256, 1) void proj_kernel(
    const float* __restrict__ x,
    const float* __restrict__ Wq, const float* __restrict__ bq,
    const float* __restrict__ Wk, const float* __restrict__ bk,
    const float* __restrict__ Wv, const float* __restrict__ bv)
{
    extern __shared__ char smraw[];
    float* Xs = (float*)smraw;                 // [64][512]
    u64*   Wr = (u64*)(smraw + C_*512*4);      // [c][o] replicated pairs

    const int b   = blockIdx.y;
    const int px0 = blockIdx.x * 512;
    const int tid = threadIdx.x;
    const int og  = tid >> 5;    // warp id = output-channel group (8 ch)
    const int ln  = tid & 31;    // lane = pixel-pair column

    // Load X tile: 64 channel rows x 512 px (rows stride HW in gmem)
    const float* xb = x + (size_t)b * C_ * HW_ + px0;
    #pragma unroll 4
    for (int e = tid; e < C_ * 512 / 4; e += 256) {
        int c = e >> 7, col = e & 127;
        ((float4*)Xs)[c * 128 + col] = *((const float4*)(xb + c * HW_) + col);
    }

    for (int m = 0; m < 3; m++) {
        const float* Wm   = (m == 0) ? Wq : (m == 1) ? Wk : Wv;
        const float* bm   = (m == 0) ? bq : (m == 1) ? bk : bv;
        float*       gout = (m == 0) ? g_q : (m == 1) ? g_k : g_v;

        __syncthreads();   // previous matrix's readers done before Wr overwrite
        for (int e = tid; e < C_ * C_; e += 256) {
            int o = e >> 6, c = e & 63;     // Wm is [o][c] row-major
            float w = Wm[e];
            Wr[c * 64 + o] = pack2(w, w);
        }
        __syncthreads();

        u64 acc[8][8];
        #pragma unroll
        for (int i = 0; i < 8; i++)
            #pragma unroll
            for (int j = 0; j < 8; j++) acc[i][j] = 0ull;

        const u64* WrO = Wr + og * 8;
        #pragma unroll 2
        for (int c = 0; c < C_; c++) {
            u64 w2[8], x2[8];
            #pragma unroll
            for (int i = 0; i < 8; i++) w2[i] = WrO[c * 64 + i];          // broadcast
            #pragma unroll
            for (int j = 0; j < 8; j++)
                x2[j] = *(const u64*)(Xs + c * 512 + ln * 2 + 64 * j);    // conflict-free
            #pragma unroll
            for (int i = 0; i < 8; i++)
                #pragma unroll
                for (int j = 0; j < 8; j++) ffma2(acc[i][j], w2[i], x2[j]);
        }

        #pragma unroll
        for (int i = 0; i < 8; i++) {
            int o = og * 8 + i;
            float bias = bm[o];
            float* orow = gout + ((size_t)b * C_ + o) * HW_ + px0 + ln * 2;
            #pragma unroll
            for (int j = 0; j < 8; j++) {
                float2 f = unpack2(acc[i][j]);
                *(float2*)(orow + 64 * j) = make_float2(f.x + bias, f.y + bias);
            }
        }
    }
}

// ---------------------------------------------------------------------------
// Kernel 2: per-(b,c) slice attention. Grid 2048 CTAs x 256 threads.
// smem: qs[128][130], ks[128][130], vs[128][128]  (198656 B)
// scores: 128x128x128 matmul, f32x2-paired over reduction dim w (natural pairs).
// softmax in registers via 16-lane shuffles; attn staged into qs; AV matmul;
// fused residual + store.
// ---------------------------------------------------------------------------
#define QP 130
#define ATTN_SMEM ((2 * 128 * QP + 128 * 128) * 4)

__global__ __launch_bounds__(256, 1) void attn_kernel(
    const float* __restrict__ x, float* __restrict__ out)
{
    extern __shared__ float sm[];
    float* qs = sm;                    // [128][QP]
    float* ks = sm + 128 * QP;         // [128][QP]
    float* vs = sm + 2 * 128 * QP;     // [128][128]

    const int bc   = blockIdx.x;       // (b*64 + c)
    const size_t base = (size_t)bc * HW_;
    const int tid = threadIdx.x;
    const int tx  = tid & 15;          // g / w column group
    const int ty  = tid >> 4;          // h row group

    // Load q,k (pitch 130, float2) and v (pitch 128, float4)
    const float2* qg = (const float2*)(g_q + base);
    const float2* kg = (const float2*)(g_k + base);
    #pragma unroll 4
    for (int e = tid; e < 8192; e += 256) {
        int r = e >> 6, c2 = e & 63;
        *(float2*)(qs + r * QP + c2 * 2) = qg[e];
        *(float2*)(ks + r * QP + c2 * 2) = kg[e];
    }
    const float4* vg = (const float4*)(g_v + base);
    #pragma unroll 4
    for (int e = tid; e < 4096; e += 256)
        ((float4*)vs)[e] = vg[e];
    __syncthreads();

    // ---- scores[h][g] = sum_w q[h][w] k[g][w], h = ty+16i, g = tx+16j ----
    u64 acc[8][8];
    #pragma unroll
    for (int i = 0; i < 8; i++)
        #pragma unroll
        for (int j = 0; j < 8; j++) acc[i][j] = 0ull;

    #pragma unroll 2
    for (int wp = 0; wp < 64; wp++) {
        u64 q2[8], k2[8];
        #pragma unroll
        for (int i = 0; i < 8; i++)
            q2[i] = *(const u64*)(qs + (ty + 16 * i) * QP + 2 * wp);   // broadcast
        #pragma unroll
        for (int j = 0; j < 8; j++)
            k2[j] = *(const u64*)(ks + (tx + 16 * j) * QP + 2 * wp);   // conflict-free
        #pragma unroll
        for (int i = 0; i < 8; i++)
            #pragma unroll
            for (int j = 0; j < 8; j++) ffma2(acc[i][j], q2[i], k2[j]);
    }

    float s[8][8];
    #pragma unroll
    for (int i = 0; i < 8; i++)
        #pragma unroll
        for (int j = 0; j < 8; j++) {
            float2 f = unpack2(acc[i][j]);
            s[i][j] = (f.x + f.y) * 0.0078125f;   // * 1/sqrt(H*W)
        }

    // ---- softmax over g for each row h (16 tx lanes hold one row) ----
    #pragma unroll
    for (int i = 0; i < 8; i++) {
        float mx = s[i][0];
        #pragma unroll
        for (int j = 1; j < 8; j++) mx = fmaxf(mx, s[i][j]);
        #pragma unroll
        for (int off = 8; off >= 1; off >>= 1)
            mx = fmaxf(mx, __shfl_xor_sync(0xffffffffu, mx, off));
        float sum = 0.f;
        #pragma unroll
        for (int j = 0; j < 8; j++) { s[i][j] = __expf(s[i][j] - mx); sum += s[i][j]; }
        #pragma unroll
        for (int off = 8; off >= 1; off >>= 1)
            sum += __shfl_xor_sync(0xffffffffu, sum, off);
        float rin = 1.0f / sum;
        #pragma unroll
        for (int j = 0; j < 8; j++) s[i][j] *= rin;
    }

    __syncthreads();   // everyone done reading qs before reuse as attn buffer
    #pragma unroll
    for (int i = 0; i < 8; i++)
        #pragma unroll
        for (int j = 0; j < 8; j++)
            qs[(ty + 16 * i) * QP + (tx + 16 * j)] = s[i][j];
    __syncthreads();

    // ---- out[h][w] = sum_g attn[h][g] v[g][w] + x[h][w] ----
    // h = ty+16i, w pairs at tx*2 + 32*jp
    u64 acco[8][4];
    #pragma unroll
    for (int i = 0; i < 8; i++)
        #pragma unroll
        for (int jp = 0; jp < 4; jp++) acco[i][jp] = 0ull;

    #pragma unroll 2
    for (int g = 0; g < 128; g++) {
        u64 v2[4];
        #pragma unroll
        for (int jp = 0; jp < 4; jp++)
            v2[jp] = *(const u64*)(vs + g * 128 + tx * 2 + 32 * jp);   // conflict-free
        #pragma unroll
        for (int i = 0; i < 8; i++) {
            float a = qs[(ty + 16 * i) * QP + g];                      // broadcast
            u64 a2 = pack2(a, a);
            #pragma unroll
            for (int jp = 0; jp < 4; jp++) ffma2(acco[i][jp], a2, v2[jp]);
        }
    }

    const float* xg = x + base;
    float* og = out + base;
    #pragma unroll
    for (int i = 0; i < 8; i++) {
        int h = ty + 16 * i;
        #pragma unroll
        for (int jp = 0; jp < 4; jp++) {
            int w0 = tx * 2 + 32 * jp;
            float2 xv = *(const float2*)(xg + h * W_ + w0);
            float2 f  = unpack2(acco[i][jp]);
            *(float2*)(og + h * W_ + w0) = make_float2(f.x + xv.x, f.y + xv.y);
        }
    }
}

// ---------------------------------------------------------------------------
extern "C" void kernel_launch(void* const* d_in, const int* in_sizes, int n_in,
                              void* d_out, int out_size)
{
    const float* x  = (const float*)d_in[0];
    const float* Wq = (const float*)d_in[1];
    const float* bq = (const float*)d_in[2];
    const float* Wk = (const float*)d_in[3];
    const float* bk = (const float*)d_in[4];
    const float* Wv = (const float*)d_in[5];
    const float* bv = (const float*)d_in[6];
    float* out = (float*)d_out;

    cudaFuncSetAttribute(proj_kernel, cudaFuncAttributeMaxDynamicSharedMemorySize, PROJ_SMEM);
    cudaFuncSetAttribute(attn_kernel, cudaFuncAttributeMaxDynamicSharedMemorySize, ATTN_SMEM);

    dim3 g1(HW_ / 512, B_);
    proj_kernel<<<g1, 256, PROJ_SMEM>>>(x, Wq, bq, Wk, bk, Wv, bv);
    attn_kernel<<<B_ * C_, 256, ATTN_SMEM>>>(x, out);
}

// round 4
// speedup vs baseline: 1.7968x; 1.7968x over previous
#include <cuda_runtime.h>
#include <cstdint>

#define B_ 32
#define C_ 64
#define H_ 128
#define W_ 128
#define HW_ (H_*W_)
#define NTOT_ (B_*C_*HW_)

// q,k,v scratch (tf32-rounded fp32 bit patterns)
__device__ float g_q[NTOT_];
__device__ float g_k[NTOT_];
__device__ float g_v[NTOT_];

// ---------------- tf32 helpers ----------------
__device__ __forceinline__ uint32_t f2tf32(float f) {
    uint32_t r; asm("cvt.rna.tf32.f32 %0, %1;" : "=r"(r) : "f"(f)); return r;
}
// D += A(16x8 row) * B(8x8 col), tf32 inputs, fp32 accum
__device__ __forceinline__ void mma_tf32(float* d, const uint32_t* a, const uint32_t* b) {
    asm volatile("mma.sync.aligned.m16n8k8.row.col.f32.tf32.tf32.f32 "
        "{%0,%1,%2,%3}, {%4,%5,%6,%7}, {%8,%9}, {%0,%1,%2,%3};"
        : "+f"(d[0]), "+f"(d[1]), "+f"(d[2]), "+f"(d[3])
        : "r"(a[0]), "r"(a[1]), "r"(a[2]), "r"(a[3]), "r"(b[0]), "r"(b[1]));
}

// ---------------------------------------------------------------------------
// Kernel 1: q/k/v = W @ x + b via tf32 HMMA.
// Grid (128, 32), 256 thr (8 warps). Tile: M=64 (o), N=128 (px), K=64 (c).
// Warp grid 4m x 2n: warp = 16 rows x 64 px (8 ntiles).
// smem: Xs[64][136] + 3 x Ws[64][68]  (fp32/tf32 bits) = 87040 B -> 2 CTA/SM.
// ---------------------------------------------------------------------------
#define XP 136   // ≡ 8 (mod 32): conflict-free B-fragment LDS
#define WP 68    // ≡ 4 (mod 32): conflict-free A-fragment LDS
#define PROJ_SMEM ((C_*XP + 3*C_*WP) * 4)

__global__ __launch_bounds__(256, 2) void proj_kernel(
    const float* __restrict__ x,
    const float* __restrict__ Wq, const float* __restrict__ bq,
    const float* __restrict__ Wk, const float* __restrict__ bk,
    const float* __restrict__ Wv, const float* __restrict__ bv)
{
    extern __shared__ float sp[];
    uint32_t* Xs = (uint32_t*)sp;              // [64][XP]
    uint32_t* Ws = (uint32_t*)(sp + C_ * XP);  // 3 x [64][WP]

    const int b   = blockIdx.y;
    const int px0 = blockIdx.x * 128;
    const int tid = threadIdx.x;
    const int w   = tid >> 5;
    const int lane = tid & 31;
    const int g   = lane >> 2;   // groupID
    const int tg  = lane & 3;    // threadID_in_group
    const int m0  = (w & 3) * 16;
    const int n0  = (w >> 2) * 64;

    // Fill X tile (cvt to tf32)
    const float* xb = x + (size_t)b * C_ * HW_ + px0;
    #pragma unroll 4
    for (int e = tid; e < C_ * 32; e += 256) {   // 64 rows x 32 float4
        int r = e >> 5, c4 = e & 31;
        float4 v = *((const float4*)(xb + r * HW_) + c4);
        uint4 t = make_uint4(f2tf32(v.x), f2tf32(v.y), f2tf32(v.z), f2tf32(v.w));
        *(uint4*)(Xs + r * XP + c4 * 4) = t;
    }
    // Fill 3 W tiles (cvt to tf32)
    #pragma unroll 4
    for (int e = tid; e < 3 * C_ * C_; e += 256) {
        int mtx = e >> 12, i = e & 4095;
        const float* Wm = (mtx == 0) ? Wq : (mtx == 1) ? Wk : Wv;
        Ws[mtx * C_ * WP + (i >> 6) * WP + (i & 63)] = f2tf32(Wm[i]);
    }
    __syncthreads();

    for (int mtx = 0; mtx < 3; mtx++) {
        const uint32_t* Wt = Ws + mtx * C_ * WP;
        float acc[8][4];
        #pragma unroll
        for (int nt = 0; nt < 8; nt++)
            #pragma unroll
            for (int j = 0; j < 4; j++) acc[nt][j] = 0.f;

        #pragma unroll
        for (int k0 = 0; k0 < 64; k0 += 8) {
            uint32_t a[4];
            a[0] = Wt[(m0 + g) * WP + k0 + tg];
            a[1] = Wt[(m0 + g + 8) * WP + k0 + tg];
            a[2] = Wt[(m0 + g) * WP + k0 + tg + 4];
            a[3] = Wt[(m0 + g + 8) * WP + k0 + tg + 4];
            #pragma unroll
            for (int nt = 0; nt < 8; nt++) {
                uint32_t bb[2];
                bb[0] = Xs[(k0 + tg) * XP + n0 + nt * 8 + g];
                bb[1] = Xs[(k0 + tg + 4) * XP + n0 + nt * 8 + g];
                mma_tf32(acc[nt], a, bb);
            }
        }

        const float* bm = (mtx == 0) ? bq : (mtx == 1) ? bk : bv;
        float* gout = ((mtx == 0) ? g_q : (mtx == 1) ? g_k : g_v)
                      + (size_t)b * C_ * HW_ + px0;
        const float bias0 = bm[m0 + g], bias1 = bm[m0 + g + 8];
        #pragma unroll
        for (int nt = 0; nt < 8; nt++) {
            int col = n0 + nt * 8 + 2 * tg;
            uint2 o0 = make_uint2(f2tf32(acc[nt][0] + bias0), f2tf32(acc[nt][1] + bias0));
            *(uint2*)(gout + (m0 + g) * HW_ + col) = o0;
            uint2 o1 = make_uint2(f2tf32(acc[nt][2] + bias1), f2tf32(acc[nt][3] + bias1));
            *(uint2*)(gout + (m0 + g + 8) * HW_ + col) = o1;
        }
        __syncthreads();   // keep Ws/Xs stable vs any reordering (cheap)
    }
}

// ---------------------------------------------------------------------------
// Kernel 2: per-(b,c) attention via tf32 HMMA. Grid 2048, 256 thr (8 warps).
// Warp w owns output rows 16w..16w+15 in BOTH matmuls -> softmax is
// quad-shuffle only; P-write/read is warp-local (__syncwarp).
// smem: Q/P [128][132], K [128][132], V [128][136]  = 204800 B.
// ---------------------------------------------------------------------------
#define QP2 132   // A-operand pitch (≡4 mod 32)
#define KP2 132   // K used as B with n->rows: needs ≡4 mod 32
#define VP2 136   // V used as B with k->rows: needs ≡8 mod 32
#define ATTN_SMEM ((128*QP2 + 128*KP2 + 128*VP2) * 4)

__global__ __launch_bounds__(256) void attn_kernel(
    const float* __restrict__ x, float* __restrict__ out)
{
    extern __shared__ float sa[];
    uint32_t* Qs = (uint32_t*)sa;              // Q, later P
    uint32_t* Ks = Qs + 128 * QP2;
    uint32_t* Vs = Ks + 128 * KP2;

    const size_t base = (size_t)blockIdx.x * HW_;
    const int tid = threadIdx.x;
    const int wid = tid >> 5;
    const int lane = tid & 31;
    const int g  = lane >> 2;
    const int tg = lane & 3;
    const int m0 = wid * 16;

    // Fill Q,K,V (already tf32 bits in gmem) — straight uint4 copies
    const uint4* qg = (const uint4*)(g_q + base);
    const uint4* kg = (const uint4*)(g_k + base);
    const uint4* vg = (const uint4*)(g_v + base);
    #pragma unroll 4
    for (int e = tid; e < 4096; e += 256) {
        int r = e >> 5, c4 = (e & 31) * 4;
        *(uint4*)(Qs + r * QP2 + c4) = qg[e];
        *(uint4*)(Ks + r * KP2 + c4) = kg[e];
        *(uint4*)(Vs + r * VP2 + c4) = vg[e];
    }
    __syncthreads();

    // ---- MM1: S[h][n] = sum_w Q[h][w] K[n][w]  (h = m0+g / m0+g+8) ----
    float acc[16][4];
    #pragma unroll
    for (int nt = 0; nt < 16; nt++)
        #pragma unroll
        for (int j = 0; j < 4; j++) acc[nt][j] = 0.f;

    #pragma unroll
    for (int k0 = 0; k0 < 128; k0 += 8) {
        uint32_t a[4];
        a[0] = Qs[(m0 + g) * QP2 + k0 + tg];
        a[1] = Qs[(m0 + g + 8) * QP2 + k0 + tg];
        a[2] = Qs[(m0 + g) * QP2 + k0 + tg + 4];
        a[3] = Qs[(m0 + g + 8) * QP2 + k0 + tg + 4];
        #pragma unroll
        for (int nt = 0; nt < 16; nt++) {
            uint32_t bb[2];
            bb[0] = Ks[(nt * 8 + g) * KP2 + k0 + tg];
            bb[1] = Ks[(nt * 8 + g) * KP2 + k0 + tg + 4];
            mma_tf32(acc[nt], a, bb);
        }
    }

    // ---- softmax (logits tiny: skip max-sub). Unnormalized exp -> P. ----
    const float scale = 0.0078125f;   // 1/sqrt(H*W)
    float sum0 = 0.f, sum1 = 0.f;
    #pragma unroll
    for (int nt = 0; nt < 16; nt++) {
        acc[nt][0] = __expf(acc[nt][0] * scale);
        acc[nt][1] = __expf(acc[nt][1] * scale);
        acc[nt][2] = __expf(acc[nt][2] * scale);
        acc[nt][3] = __expf(acc[nt][3] * scale);
        sum0 += acc[nt][0] + acc[nt][1];
        sum1 += acc[nt][2] + acc[nt][3];
    }
    sum0 += __shfl_xor_sync(0xffffffffu, sum0, 1);
    sum0 += __shfl_xor_sync(0xffffffffu, sum0, 2);
    sum1 += __shfl_xor_sync(0xffffffffu, sum1, 1);
    sum1 += __shfl_xor_sync(0xffffffffu, sum1, 2);
    const float rin0 = 1.0f / sum0, rin1 = 1.0f / sum1;

    __syncwarp();   // all lanes done reading Q rows m0.. before overwrite
    #pragma unroll
    for (int nt = 0; nt < 16; nt++) {
        *(uint2*)(Qs + (m0 + g) * QP2 + nt * 8 + 2 * tg) =
            make_uint2(f2tf32(acc[nt][0]), f2tf32(acc[nt][1]));
        *(uint2*)(Qs + (m0 + g + 8) * QP2 + nt * 8 + 2 * tg) =
            make_uint2(f2tf32(acc[nt][2]), f2tf32(acc[nt][3]));
    }
    __syncwarp();   // P visible to all lanes of this warp

    // ---- MM2: O[h][w] = sum_n P[h][n] V[n][w] ----
    float o[16][4];
    #pragma unroll
    for (int nt = 0; nt < 16; nt++)
        #pragma unroll
        for (int j = 0; j < 4; j++) o[nt][j] = 0.f;

    #pragma unroll
    for (int k0 = 0; k0 < 128; k0 += 8) {
        uint32_t a[4];
        a[0] = Qs[(m0 + g) * QP2 + k0 + tg];
        a[1] = Qs[(m0 + g + 8) * QP2 + k0 + tg];
        a[2] = Qs[(m0 + g) * QP2 + k0 + tg + 4];
        a[3] = Qs[(m0 + g + 8) * QP2 + k0 + tg + 4];
        #pragma unroll
        for (int nt = 0; nt < 16; nt++) {
            uint32_t bb[2];
            bb[0] = Vs[(k0 + tg) * VP2 + nt * 8 + g];
            bb[1] = Vs[(k0 + tg + 4) * VP2 + nt * 8 + g];
            mma_tf32(o[nt], a, bb);
        }
    }

    // ---- epilogue: normalize + residual + store ----
    const float* xg = x + base;
    float* og = out + base;
    #pragma unroll
    for (int nt = 0; nt < 16; nt++) {
        int col = nt * 8 + 2 * tg;
        float2 xv0 = *(const float2*)(xg + (m0 + g) * W_ + col);
        *(float2*)(og + (m0 + g) * W_ + col) =
            make_float2(o[nt][0] * rin0 + xv0.x, o[nt][1] * rin0 + xv0.y);
        float2 xv1 = *(const float2*)(xg + (m0 + g + 8) * W_ + col);
        *(float2*)(og + (m0 + g + 8) * W_ + col) =
            make_float2(o[nt][2] * rin1 + xv1.x, o[nt][3] * rin1 + xv1.y);
    }
}

// ---------------------------------------------------------------------------
extern "C" void kernel_launch(void* const* d_in, const int* in_sizes, int n_in,
                              void* d_out, int out_size)
{
    const float* x  = (const float*)d_in[0];
    const float* Wq = (const float*)d_in[1];
    const float* bq = (const float*)d_in[2];
    const float* Wk = (const float*)d_in[3];
    const float* bk = (const float*)d_in[4];
    const float* Wv = (const float*)d_in[5];
    const float* bv = (const float*)d_in[6];
    float* out = (float*)d_out;

    cudaFuncSetAttribute(proj_kernel, cudaFuncAttributeMaxDynamicSharedMemorySize, PROJ_SMEM);
    cudaFuncSetAttribute(attn_kernel, cudaFuncAttributeMaxDynamicSharedMemorySize, ATTN_SMEM);

    dim3 g1(HW_ / 128, B_);
    proj_kernel<<<g1, 256, PROJ_SMEM>>>(x, Wq, bq, Wk, bk, Wv, bv);
    attn_kernel<<<B_ * C_, 256, ATTN_SMEM>>>(x, out);
}

// round 5
// speedup vs baseline: 2.4510x; 1.3641x over previous
#include <cuda_runtime.h>
#include <cuda_fp16.h>
#include <cstdint>

#define B_ 32
#define C_ 64
#define H_ 128
#define W_ 128
#define HW_ (H_*W_)
#define NTOT_ (B_*C_*HW_)

#define GRP 4                 // batches per group (L2-resident qkv)
#define NGRP (B_/GRP)

// q,k,v scratch in fp16
__device__ __half g_q[NTOT_];
__device__ __half g_k[NTOT_];
__device__ __half g_v[NTOT_];

// ---------------- helpers ----------------
__device__ __forceinline__ uint32_t smem_u32(const void* p) {
    uint32_t a;
    asm("{ .reg .u64 t; cvta.to.shared.u64 t, %1; cvt.u32.u64 %0, t; }" : "=r"(a) : "l"(p));
    return a;
}
__device__ __forceinline__ uint32_t packh2(float lo, float hi) {
    __half2 h = __floats2half2_rn(lo, hi);
    return *reinterpret_cast<uint32_t*>(&h);
}
__device__ __forceinline__ void ldmx4(uint32_t* r, uint32_t addr) {
    asm volatile("ldmatrix.sync.aligned.m8n8.x4.shared.b16 {%0,%1,%2,%3}, [%4];"
        : "=r"(r[0]), "=r"(r[1]), "=r"(r[2]), "=r"(r[3]) : "r"(addr));
}
__device__ __forceinline__ void ldmx4t(uint32_t* r, uint32_t addr) {
    asm volatile("ldmatrix.sync.aligned.m8n8.x4.trans.shared.b16 {%0,%1,%2,%3}, [%4];"
        : "=r"(r[0]), "=r"(r[1]), "=r"(r[2]), "=r"(r[3]) : "r"(addr));
}
// D += A(16x16) * B(16x8), fp16 in, fp32 accum
__device__ __forceinline__ void mma_f16(float* d, const uint32_t* a, const uint32_t* b) {
    asm volatile("mma.sync.aligned.m16n8k16.row.col.f32.f16.f16.f32 "
        "{%0,%1,%2,%3}, {%4,%5,%6,%7}, {%8,%9}, {%0,%1,%2,%3};"
        : "+f"(d[0]), "+f"(d[1]), "+f"(d[2]), "+f"(d[3])
        : "r"(a[0]), "r"(a[1]), "r"(a[2]), "r"(a[3]), "r"(b[0]), "r"(b[1]));
}

// ---------------------------------------------------------------------------
// Kernel 1: q/k/v = W @ x + b, fp16 HMMA, fp16 outputs.
// Grid (128, GRP), 256 thr. Tile M=64(o) x N=128(px) x K=64(c).
// smem: Xs[64][136]h + 3x Ws[64][72]h = 45056 B -> 4 CTAs/SM.
// ---------------------------------------------------------------------------
#define XPH 136   // 272B rows: ldmatrix row phase r*4 mod 32 -> conflict-free
#define WPH 72    // 144B rows: phase r*4 mod 32 -> conflict-free
#define PROJ_SMEM (64*XPH*2 + 3*64*WPH*2)

__global__ __launch_bounds__(256, 4) void proj_kernel(
    const float* __restrict__ x,
    const float* __restrict__ Wq, const float* __restrict__ bq,
    const float* __restrict__ Wk, const float* __restrict__ bk,
    const float* __restrict__ Wv, const float* __restrict__ bv,
    int b0)
{
    extern __shared__ __half smp[];
    __half* Xs = smp;                     // [64][XPH]
    __half* Ws = smp + 64 * XPH;          // 3 x [64][WPH]
    const uint32_t smb = smem_u32(smp);
    const uint32_t XsB = smb, WsB = smb + 64 * XPH * 2;

    const int b    = blockIdx.y + b0;
    const int px0  = blockIdx.x * 128;
    const int tid  = threadIdx.x;
    const int w    = tid >> 5;
    const int lane = tid & 31;
    const int g    = lane >> 2;
    const int tg   = lane & 3;
    const int m0   = (w & 3) * 16;
    const int n0   = (w >> 2) * 64;

    // Fill X tile (fp32 -> fp16)
    const float* xb = x + (size_t)b * C_ * HW_ + px0;
    #pragma unroll 4
    for (int e = tid; e < 2048; e += 256) {
        int r = e >> 5, c4 = e & 31;
        float4 v = *((const float4*)(xb + r * HW_) + c4);
        *(uint2*)(Xs + r * XPH + c4 * 4) =
            make_uint2(packh2(v.x, v.y), packh2(v.z, v.w));
    }
    // Fill 3 W tiles
    #pragma unroll 4
    for (int e = tid; e < 3 * 2048; e += 256) {
        int mtx = e >> 11, i = e & 2047;
        int o = i >> 5, c2 = i & 31;
        const float* Wm = (mtx == 0) ? Wq : (mtx == 1) ? Wk : Wv;
        float2 wv = *((const float2*)(Wm + o * 64) + c2);
        *(uint32_t*)(Ws + mtx * 64 * WPH + o * WPH + c2 * 2) = packh2(wv.x, wv.y);
    }
    __syncthreads();

    const int rsel = lane & 15;           // ldmatrix row select
    const int csel = (lane & 16) >> 1;    // ldmatrix col-block select (0/8)

    #pragma unroll
    for (int mtx = 0; mtx < 3; mtx++) {
        const uint32_t WtB = WsB + (uint32_t)mtx * 64 * WPH * 2;
        float acc[8][4];
        #pragma unroll
        for (int nt = 0; nt < 8; nt++)
            #pragma unroll
            for (int j = 0; j < 4; j++) acc[nt][j] = 0.f;

        #pragma unroll
        for (int k0 = 0; k0 < 64; k0 += 16) {
            uint32_t a[4];
            ldmx4(a, WtB + (uint32_t)((m0 + rsel) * WPH + k0 + csel) * 2);
            #pragma unroll
            for (int ntp = 0; ntp < 4; ntp++) {
                uint32_t bb[4];
                ldmx4t(bb, XsB + (uint32_t)((k0 + rsel) * XPH + n0 + ntp * 16 + csel) * 2);
                mma_f16(acc[2 * ntp],     a, bb);
                mma_f16(acc[2 * ntp + 1], a, bb + 2);
            }
        }

        const float* bm = (mtx == 0) ? bq : (mtx == 1) ? bk : bv;
        __half* gout = ((mtx == 0) ? g_q : (mtx == 1) ? g_k : g_v);
        float bias0 = bm[m0 + g], bias1 = bm[m0 + g + 8];
        __half* orow0 = gout + ((size_t)b * C_ + m0 + g) * HW_ + px0;
        __half* orow1 = orow0 + 8 * HW_;
        #pragma unroll
        for (int nt = 0; nt < 8; nt++) {
            int col = n0 + nt * 8 + 2 * tg;
            *(uint32_t*)(orow0 + col) = packh2(acc[nt][0] + bias0, acc[nt][1] + bias0);
            *(uint32_t*)(orow1 + col) = packh2(acc[nt][2] + bias1, acc[nt][3] + bias1);
        }
    }
}

// ---------------------------------------------------------------------------
// Kernel 2: per-(b,c) attention, fp16 HMMA, register-resident P.
// Grid GRP*64, 256 thr (8 warps; warp w owns rows 16w for BOTH matmuls).
// smem: Q,K,V fp16 [128][136] each = 104448 B -> 2 CTAs/SM.
// ---------------------------------------------------------------------------
#define PH 136
#define ATTN_SMEM (3 * 128 * PH * 2)

__global__ __launch_bounds__(256, 2) void attn_kernel(
    const float* __restrict__ x, float* __restrict__ out, int bc0)
{
    extern __shared__ __half sma[];
    __half* Qs = sma;
    __half* Ks = sma + 128 * PH;
    __half* Vs = sma + 2 * 128 * PH;
    const uint32_t smb = smem_u32(sma);
    const uint32_t QsB = smb, KsB = smb + 128 * PH * 2, VsB = smb + 2 * 128 * PH * 2;

    const int bc = bc0 + blockIdx.x;
    const size_t base = (size_t)bc * HW_;
    const int tid  = threadIdx.x;
    const int wid  = tid >> 5;
    const int lane = tid & 31;
    const int g    = lane >> 2;
    const int tg   = lane & 3;
    const int m0   = wid * 16;
    const int rsel = lane & 15;
    const int csel = (lane & 16) >> 1;

    // Fill Q,K,V (uint4 = 8 halves)
    const uint4* qg = (const uint4*)(g_q + base);
    const uint4* kg = (const uint4*)(g_k + base);
    const uint4* vg = (const uint4*)(g_v + base);
    #pragma unroll 4
    for (int e = tid; e < 2048; e += 256) {
        int r = e >> 4, c8 = (e & 15) * 8;
        *(uint4*)(Qs + r * PH + c8) = qg[e];
        *(uint4*)(Ks + r * PH + c8) = kg[e];
        *(uint4*)(Vs + r * PH + c8) = vg[e];
    }
    __syncthreads();

    // ---- MM1: S[h][n] = sum_w Q[h][w] K[n][w] ----
    float acc[16][4];
    #pragma unroll
    for (int nt = 0; nt < 16; nt++)
        #pragma unroll
        for (int j = 0; j < 4; j++) acc[nt][j] = 0.f;

    #pragma unroll
    for (int ks = 0; ks < 8; ks++) {
        const int k0 = ks * 16;
        uint32_t aq[4];
        ldmx4(aq, QsB + (uint32_t)((m0 + rsel) * PH + k0 + csel) * 2);
        #pragma unroll
        for (int ntp = 0; ntp < 8; ntp++) {
            uint32_t kb[4];
            // lanes 0-7: K[n0+l][k0], 8-15: K[n0+l][k0+8], 16-23: K[n0+8+l][k0], 24-31: K[n0+8+l][k0+8]
            ldmx4(kb, KsB + (uint32_t)((ntp * 16 + csel + (lane & 7)) * PH + k0 + (lane & 8)) * 2);
            mma_f16(acc[2 * ntp],     aq, kb);
            mma_f16(acc[2 * ntp + 1], aq, kb + 2);
        }
    }

    // ---- softmax (logits tiny: skip max-sub); P packed to fp16 in regs ----
    const float scale = 0.0078125f;
    float sum0 = 0.f, sum1 = 0.f;
    uint32_t ph[16][2];
    #pragma unroll
    for (int nt = 0; nt < 16; nt++) {
        float e0 = __expf(acc[nt][0] * scale);
        float e1 = __expf(acc[nt][1] * scale);
        float e2 = __expf(acc[nt][2] * scale);
        float e3 = __expf(acc[nt][3] * scale);
        sum0 += e0 + e1;  sum1 += e2 + e3;
        ph[nt][0] = packh2(e0, e1);       // row g,  A-frag a0/a2 source
        ph[nt][1] = packh2(e2, e3);       // row g+8
    }
    sum0 += __shfl_xor_sync(0xffffffffu, sum0, 1);
    sum0 += __shfl_xor_sync(0xffffffffu, sum0, 2);
    sum1 += __shfl_xor_sync(0xffffffffu, sum1, 1);
    sum1 += __shfl_xor_sync(0xffffffffu, sum1, 2);
    const float rin0 = 1.0f / sum0, rin1 = 1.0f / sum1;

    // ---- MM2: O[h][w] = sum_n P[h][n] V[n][w], two column halves ----
    const float* xg = x + base;
    float* og = out + base;
    #pragma unroll
    for (int hf = 0; hf < 2; hf++) {
        const int w00 = hf * 64;
        float o[8][4];
        #pragma unroll
        for (int wt = 0; wt < 8; wt++)
            #pragma unroll
            for (int j = 0; j < 4; j++) o[wt][j] = 0.f;

        #pragma unroll
        for (int s = 0; s < 8; s++) {
            const int k0 = s * 16;
            uint32_t a[4] = { ph[2*s][0], ph[2*s][1], ph[2*s+1][0], ph[2*s+1][1] };
            #pragma unroll
            for (int wtp = 0; wtp < 4; wtp++) {
                uint32_t vb[4];
                ldmx4t(vb, VsB + (uint32_t)((k0 + rsel) * PH + w00 + wtp * 16 + csel) * 2);
                mma_f16(o[2 * wtp],     a, vb);
                mma_f16(o[2 * wtp + 1], a, vb + 2);
            }
        }

        #pragma unroll
        for (int wt = 0; wt < 8; wt++) {
            int col = w00 + wt * 8 + 2 * tg;
            float2 xv0 = *(const float2*)(xg + (m0 + g) * W_ + col);
            *(float2*)(og + (m0 + g) * W_ + col) =
                make_float2(o[wt][0] * rin0 + xv0.x, o[wt][1] * rin0 + xv0.y);
            float2 xv1 = *(const float2*)(xg + (m0 + g + 8) * W_ + col);
            *(float2*)(og + (m0 + g + 8) * W_ + col) =
                make_float2(o[wt][2] * rin1 + xv1.x, o[wt][3] * rin1 + xv1.y);
        }
    }
}

// ---------------------------------------------------------------------------
extern "C" void kernel_launch(void* const* d_in, const int* in_sizes, int n_in,
                              void* d_out, int out_size)
{
    const float* x  = (const float*)d_in[0];
    const float* Wq = (const float*)d_in[1];
    const float* bq = (const float*)d_in[2];
    const float* Wk = (const float*)d_in[3];
    const float* bk = (const float*)d_in[4];
    const float* Wv = (const float*)d_in[5];
    const float* bv = (const float*)d_in[6];
    float* out = (float*)d_out;

    cudaFuncSetAttribute(proj_kernel, cudaFuncAttributeMaxDynamicSharedMemorySize, PROJ_SMEM);
    cudaFuncSetAttribute(attn_kernel, cudaFuncAttributeMaxDynamicSharedMemorySize, ATTN_SMEM);

    // Batch-grouped launches: each group's q/k/v (25 MB fp16) stays L2-resident
    // between its proj and attn.
    for (int grp = 0; grp < NGRP; grp++) {
        dim3 g1(HW_ / 128, GRP);
        proj_kernel<<<g1, 256, PROJ_SMEM>>>(x, Wq, bq, Wk, bk, Wv, bv, grp * GRP);
        attn_kernel<<<GRP * 64, 256, ATTN_SMEM>>>(x, out, grp * GRP * 64);
    }
}